// round 4
// baseline (speedup 1.0000x reference)
#include <cuda_runtime.h>
#include <cuda_bf16.h>

// RNN autoencoder (GRU enc/dec), batch-parallel persistent-state design.
// Encoder kernel: LN + 2-layer GRU + fc_enc(tanh) -> z (global scratch + d_out tail).
// Decoder kernel: fc_dec gather (permuted reshape) + 2-layer autoregressive GRU
//                 + fc_out -> recon (d_out head).
// Each block owns MB=8 batch rows; thread j owns hidden unit j for all rows.
// Packed fma.rn.f32x2 doubles fp32 FMA issue rate (PTX-only path on sm_103a).

#define TT   180
#define HH   256
#define BB   512
#define LATD 128
#define MB   8
#define NB   (BB / MB)   // 64 blocks

__device__ float g_z[BB * LATD];

__device__ __forceinline__ void fma2(unsigned long long& acc,
                                     unsigned long long a,
                                     unsigned long long b) {
    asm("fma.rn.f32x2 %0, %1, %2, %0;" : "+l"(acc) : "l"(a), "l"(b));
}
__device__ __forceinline__ float psum(unsigned long long a) {
    float lo, hi;
    asm("mov.b64 {%0, %1}, %2;" : "=f"(lo), "=f"(hi) : "l"(a));
    return lo + hi;
}
__device__ __forceinline__ float sigm(float x) {
    return __fdividef(1.f, 1.f + __expf(-x));
}
__device__ __forceinline__ float tanhe(float x) {
    // 1 - 2/(e^{2x}+1): correct saturation at +-inf, ~1e-6 rel err
    return 1.f - __fdividef(2.f, __expf(2.f * x) + 1.f);
}

// ---------------------------------------------------------------------------
// Encoder
// ---------------------------------------------------------------------------
__global__ __launch_bounds__(256)
void enc_kernel(const float* __restrict__ x,
                const float* __restrict__ ln_w, const float* __restrict__ ln_b,
                const float* __restrict__ Wih0, const float* __restrict__ Whh0,
                const float* __restrict__ bih0, const float* __restrict__ bhh0,
                const float* __restrict__ Wih1, const float* __restrict__ Whh1,
                const float* __restrict__ bih1, const float* __restrict__ bhh1,
                const float* __restrict__ fce_w, const float* __restrict__ fce_b,
                float* __restrict__ z_out, int write_zout)
{
    __shared__ __align__(16) float sh_h0[MB][HH];
    __shared__ __align__(16) float sh_h1[MB][HH];
    __shared__ __align__(16) float sh_x[MB][TT][2];

    const int j    = threadIdx.x;
    const int base = blockIdx.x * MB;
    const int w    = j >> 5;
    const int lane = j & 31;

    #pragma unroll
    for (int b = 0; b < MB; b++) { sh_h0[b][j] = 0.f; sh_h1[b][j] = 0.f; }

    // LayerNorm over (T,2) jointly per batch row; warp w handles row w.
    {
        const int b = w;
        const float* xr = x + (size_t)(base + b) * TT * 2;
        float s = 0.f, s2 = 0.f;
        for (int i = lane; i < TT * 2; i += 32) {
            float v = xr[i]; s += v; s2 += v * v;
        }
        #pragma unroll
        for (int o = 16; o > 0; o >>= 1) {
            s  += __shfl_xor_sync(0xffffffffu, s, o);
            s2 += __shfl_xor_sync(0xffffffffu, s2, o);
        }
        const float inv = 1.f / (TT * 2);
        float mu  = s * inv;
        float var = s2 * inv - mu * mu;
        float rs  = rsqrtf(var + 1e-5f);
        for (int i = lane; i < TT * 2; i += 32) {
            sh_x[b][i >> 1][i & 1] = (xr[i] - mu) * rs * ln_w[i] + ln_b[i];
        }
    }
    __syncthreads();

    // Per-thread constants
    const float e0wr0 = Wih0[j * 2 + 0],            e0wr1 = Wih0[j * 2 + 1];
    const float e0wz0 = Wih0[(HH + j) * 2 + 0],     e0wz1 = Wih0[(HH + j) * 2 + 1];
    const float e0wn0 = Wih0[(2 * HH + j) * 2 + 0], e0wn1 = Wih0[(2 * HH + j) * 2 + 1];
    const float c0r  = bih0[j] + bhh0[j];
    const float c0z  = bih0[HH + j] + bhh0[HH + j];
    const float c0in = bih0[2 * HH + j];
    const float c0hn = bhh0[2 * HH + j];
    const float c1r  = bih1[j] + bhh1[j];
    const float c1z  = bih1[HH + j] + bhh1[HH + j];
    const float c1in = bih1[2 * HH + j];
    const float c1hn = bhh1[2 * HH + j];

    const ulonglong2* W0r = (const ulonglong2*)(Whh0 + (size_t)j * HH);
    const ulonglong2* W0z = (const ulonglong2*)(Whh0 + (size_t)(HH + j) * HH);
    const ulonglong2* W0n = (const ulonglong2*)(Whh0 + (size_t)(2 * HH + j) * HH);
    const ulonglong2* U1r = (const ulonglong2*)(Wih1 + (size_t)j * HH);
    const ulonglong2* U1z = (const ulonglong2*)(Wih1 + (size_t)(HH + j) * HH);
    const ulonglong2* U1n = (const ulonglong2*)(Wih1 + (size_t)(2 * HH + j) * HH);
    const ulonglong2* W1r = (const ulonglong2*)(Whh1 + (size_t)j * HH);
    const ulonglong2* W1z = (const ulonglong2*)(Whh1 + (size_t)(HH + j) * HH);
    const ulonglong2* W1n = (const ulonglong2*)(Whh1 + (size_t)(2 * HH + j) * HH);

    for (int t = 0; t < TT; t++) {
        // ---- layer 0 (input dim 2) ----
        unsigned long long ar[MB], az[MB], an_[MB];
        #pragma unroll
        for (int b = 0; b < MB; b++) { ar[b] = 0ull; az[b] = 0ull; an_[b] = 0ull; }

        #pragma unroll 2
        for (int k = 0; k < HH / 4; k++) {
            ulonglong2 wr = __ldg(W0r + k);
            ulonglong2 wz = __ldg(W0z + k);
            ulonglong2 wn = __ldg(W0n + k);
            #pragma unroll
            for (int b = 0; b < MB; b++) {
                ulonglong2 h = *(const ulonglong2*)&sh_h0[b][k * 4];
                fma2(ar[b],  wr.x, h.x); fma2(ar[b],  wr.y, h.y);
                fma2(az[b],  wz.x, h.x); fma2(az[b],  wz.y, h.y);
                fma2(an_[b], wn.x, h.x); fma2(an_[b], wn.y, h.y);
            }
        }
        float hn0[MB];
        #pragma unroll
        for (int b = 0; b < MB; b++) {
            float x0 = sh_x[b][t][0], x1 = sh_x[b][t][1];
            float r  = sigm(psum(ar[b]) + c0r + e0wr0 * x0 + e0wr1 * x1);
            float zg = sigm(psum(az[b]) + c0z + e0wz0 * x0 + e0wz1 * x1);
            float n  = tanhe(c0in + e0wn0 * x0 + e0wn1 * x1 +
                             r * (psum(an_[b]) + c0hn));
            hn0[b] = (1.f - zg) * n + zg * sh_h0[b][j];
        }
        __syncthreads();
        #pragma unroll
        for (int b = 0; b < MB; b++) sh_h0[b][j] = hn0[b];
        __syncthreads();

        // ---- layer 1 (input = sh_h0, hidden = sh_h1) ----
        unsigned long long br_[MB], bz_[MB], bin_[MB], bhn_[MB];
        #pragma unroll
        for (int b = 0; b < MB; b++) { br_[b] = 0ull; bz_[b] = 0ull; bin_[b] = 0ull; bhn_[b] = 0ull; }

        #pragma unroll 2
        for (int k = 0; k < HH / 4; k++) {
            ulonglong2 wr = __ldg(U1r + k);
            ulonglong2 wz = __ldg(U1z + k);
            ulonglong2 wn = __ldg(U1n + k);
            #pragma unroll
            for (int b = 0; b < MB; b++) {
                ulonglong2 u = *(const ulonglong2*)&sh_h0[b][k * 4];
                fma2(br_[b],  wr.x, u.x); fma2(br_[b],  wr.y, u.y);
                fma2(bz_[b],  wz.x, u.x); fma2(bz_[b],  wz.y, u.y);
                fma2(bin_[b], wn.x, u.x); fma2(bin_[b], wn.y, u.y);
            }
        }
        #pragma unroll 2
        for (int k = 0; k < HH / 4; k++) {
            ulonglong2 wr = __ldg(W1r + k);
            ulonglong2 wz = __ldg(W1z + k);
            ulonglong2 wn = __ldg(W1n + k);
            #pragma unroll
            for (int b = 0; b < MB; b++) {
                ulonglong2 h = *(const ulonglong2*)&sh_h1[b][k * 4];
                fma2(br_[b],  wr.x, h.x); fma2(br_[b],  wr.y, h.y);
                fma2(bz_[b],  wz.x, h.x); fma2(bz_[b],  wz.y, h.y);
                fma2(bhn_[b], wn.x, h.x); fma2(bhn_[b], wn.y, h.y);
            }
        }
        float hn1[MB];
        #pragma unroll
        for (int b = 0; b < MB; b++) {
            float r  = sigm(psum(br_[b]) + c1r);
            float zg = sigm(psum(bz_[b]) + c1z);
            float n  = tanhe(psum(bin_[b]) + c1in + r * (psum(bhn_[b]) + c1hn));
            hn1[b] = (1.f - zg) * n + zg * sh_h1[b][j];
        }
        __syncthreads();
        #pragma unroll
        for (int b = 0; b < MB; b++) sh_h1[b][j] = hn1[b];
        __syncthreads();
    }

    // z = tanh(h1_final @ fce_w.T + fce_b)
    {
        const int l  = j & (LATD - 1);
        const int b0 = (j >> 7) * 4;
        const float* wl = fce_w + (size_t)l * HH;
        for (int b = b0; b < b0 + 4; b++) {
            float acc = 0.f;
            for (int k = 0; k < HH; k++) acc += wl[k] * sh_h1[b][k];
            float zz = tanhf(acc + fce_b[l]);
            g_z[(size_t)(base + b) * LATD + l] = zz;
            if (write_zout) z_out[(size_t)(base + b) * LATD + l] = zz;
        }
    }
}

// ---------------------------------------------------------------------------
// Decoder
// ---------------------------------------------------------------------------
__global__ __launch_bounds__(256)
void dec_kernel(const float* __restrict__ Wih0, const float* __restrict__ Whh0,
                const float* __restrict__ bih0, const float* __restrict__ bhh0,
                const float* __restrict__ Wih1, const float* __restrict__ Whh1,
                const float* __restrict__ bih1, const float* __restrict__ bhh1,
                const float* __restrict__ fcd_w, const float* __restrict__ fcd_b,
                const float* __restrict__ fco_w, const float* __restrict__ fco_b,
                float* __restrict__ out)
{
    __shared__ __align__(16) float sh_h0[MB][HH];
    __shared__ __align__(16) float sh_h1[MB][HH];
    __shared__ float sh_y[MB][2];

    const int j    = threadIdx.x;
    const int base = blockIdx.x * MB;
    const int w    = j >> 5;
    const int lane = j & 31;

    // Init hidden states from fc_dec(z) with the raw row-major reshape mapping:
    // dec_h[l][gb][j] = fcd_b[c'] + z[l*256 + gb/2] . fcd_w[c'],  c' = (gb&1)*256 + j
    #pragma unroll
    for (int b = 0; b < MB; b++) {
        int gb = base + b;
        int cr = ((gb & 1) << 8) + j;
        const float* wrow = fcd_w + (size_t)cr * LATD;
        const float* z0 = g_z + (size_t)(gb >> 1) * LATD;
        const float* z1 = g_z + (size_t)(256 + (gb >> 1)) * LATD;
        float a0 = fcd_b[cr], a1 = fcd_b[cr];
        for (int k = 0; k < LATD; k++) {
            float wv = wrow[k];
            a0 += wv * z0[k];
            a1 += wv * z1[k];
        }
        sh_h0[b][j] = a0;
        sh_h1[b][j] = a1;
    }
    if (j < MB * 2) sh_y[j >> 1][j & 1] = 0.f;
    __syncthreads();

    const float d0wr0 = Wih0[j * 2 + 0],            d0wr1 = Wih0[j * 2 + 1];
    const float d0wz0 = Wih0[(HH + j) * 2 + 0],     d0wz1 = Wih0[(HH + j) * 2 + 1];
    const float d0wn0 = Wih0[(2 * HH + j) * 2 + 0], d0wn1 = Wih0[(2 * HH + j) * 2 + 1];
    const float c0r  = bih0[j] + bhh0[j];
    const float c0z  = bih0[HH + j] + bhh0[HH + j];
    const float c0in = bih0[2 * HH + j];
    const float c0hn = bhh0[2 * HH + j];
    const float c1r  = bih1[j] + bhh1[j];
    const float c1z  = bih1[HH + j] + bhh1[HH + j];
    const float c1in = bih1[2 * HH + j];
    const float c1hn = bhh1[2 * HH + j];

    const ulonglong2* W0r = (const ulonglong2*)(Whh0 + (size_t)j * HH);
    const ulonglong2* W0z = (const ulonglong2*)(Whh0 + (size_t)(HH + j) * HH);
    const ulonglong2* W0n = (const ulonglong2*)(Whh0 + (size_t)(2 * HH + j) * HH);
    const ulonglong2* U1r = (const ulonglong2*)(Wih1 + (size_t)j * HH);
    const ulonglong2* U1z = (const ulonglong2*)(Wih1 + (size_t)(HH + j) * HH);
    const ulonglong2* U1n = (const ulonglong2*)(Wih1 + (size_t)(2 * HH + j) * HH);
    const ulonglong2* W1r = (const ulonglong2*)(Whh1 + (size_t)j * HH);
    const ulonglong2* W1z = (const ulonglong2*)(Whh1 + (size_t)(HH + j) * HH);
    const ulonglong2* W1n = (const ulonglong2*)(Whh1 + (size_t)(2 * HH + j) * HH);

    for (int t = 0; t < TT; t++) {
        // ---- layer 0 (input = y, dim 2) ----
        unsigned long long ar[MB], az[MB], an_[MB];
        #pragma unroll
        for (int b = 0; b < MB; b++) { ar[b] = 0ull; az[b] = 0ull; an_[b] = 0ull; }

        #pragma unroll 2
        for (int k = 0; k < HH / 4; k++) {
            ulonglong2 wr = __ldg(W0r + k);
            ulonglong2 wz = __ldg(W0z + k);
            ulonglong2 wn = __ldg(W0n + k);
            #pragma unroll
            for (int b = 0; b < MB; b++) {
                ulonglong2 h = *(const ulonglong2*)&sh_h0[b][k * 4];
                fma2(ar[b],  wr.x, h.x); fma2(ar[b],  wr.y, h.y);
                fma2(az[b],  wz.x, h.x); fma2(az[b],  wz.y, h.y);
                fma2(an_[b], wn.x, h.x); fma2(an_[b], wn.y, h.y);
            }
        }
        float hn0[MB];
        #pragma unroll
        for (int b = 0; b < MB; b++) {
            float x0 = sh_y[b][0], x1 = sh_y[b][1];
            float r  = sigm(psum(ar[b]) + c0r + d0wr0 * x0 + d0wr1 * x1);
            float zg = sigm(psum(az[b]) + c0z + d0wz0 * x0 + d0wz1 * x1);
            float n  = tanhe(c0in + d0wn0 * x0 + d0wn1 * x1 +
                             r * (psum(an_[b]) + c0hn));
            hn0[b] = (1.f - zg) * n + zg * sh_h0[b][j];
        }
        __syncthreads();
        #pragma unroll
        for (int b = 0; b < MB; b++) sh_h0[b][j] = hn0[b];
        __syncthreads();

        // ---- layer 1 ----
        unsigned long long br_[MB], bz_[MB], bin_[MB], bhn_[MB];
        #pragma unroll
        for (int b = 0; b < MB; b++) { br_[b] = 0ull; bz_[b] = 0ull; bin_[b] = 0ull; bhn_[b] = 0ull; }

        #pragma unroll 2
        for (int k = 0; k < HH / 4; k++) {
            ulonglong2 wr = __ldg(U1r + k);
            ulonglong2 wz = __ldg(U1z + k);
            ulonglong2 wn = __ldg(U1n + k);
            #pragma unroll
            for (int b = 0; b < MB; b++) {
                ulonglong2 u = *(const ulonglong2*)&sh_h0[b][k * 4];
                fma2(br_[b],  wr.x, u.x); fma2(br_[b],  wr.y, u.y);
                fma2(bz_[b],  wz.x, u.x); fma2(bz_[b],  wz.y, u.y);
                fma2(bin_[b], wn.x, u.x); fma2(bin_[b], wn.y, u.y);
            }
        }
        #pragma unroll 2
        for (int k = 0; k < HH / 4; k++) {
            ulonglong2 wr = __ldg(W1r + k);
            ulonglong2 wz = __ldg(W1z + k);
            ulonglong2 wn = __ldg(W1n + k);
            #pragma unroll
            for (int b = 0; b < MB; b++) {
                ulonglong2 h = *(const ulonglong2*)&sh_h1[b][k * 4];
                fma2(br_[b],  wr.x, h.x); fma2(br_[b],  wr.y, h.y);
                fma2(bz_[b],  wz.x, h.x); fma2(bz_[b],  wz.y, h.y);
                fma2(bhn_[b], wn.x, h.x); fma2(bhn_[b], wn.y, h.y);
            }
        }
        float hn1[MB];
        #pragma unroll
        for (int b = 0; b < MB; b++) {
            float r  = sigm(psum(br_[b]) + c1r);
            float zg = sigm(psum(bz_[b]) + c1z);
            float n  = tanhe(psum(bin_[b]) + c1in + r * (psum(bhn_[b]) + c1hn));
            hn1[b] = (1.f - zg) * n + zg * sh_h1[b][j];
        }
        __syncthreads();
        #pragma unroll
        for (int b = 0; b < MB; b++) sh_h1[b][j] = hn1[b];
        __syncthreads();

        // ---- output head: warp w handles batch row w ----
        {
            const int b = w;
            float a0 = 0.f, a1 = 0.f;
            const float* w0 = fco_w;
            const float* w1 = fco_w + HH;
            for (int k = lane; k < HH; k += 32) {
                float hv = sh_h1[b][k];
                a0 += w0[k] * hv;
                a1 += w1[k] * hv;
            }
            #pragma unroll
            for (int o = 16; o > 0; o >>= 1) {
                a0 += __shfl_xor_sync(0xffffffffu, a0, o);
                a1 += __shfl_xor_sync(0xffffffffu, a1, o);
            }
            if (lane == 0) {
                float y0 = a0 + fco_b[0];
                float y1 = a1 + fco_b[1];
                sh_y[b][0] = y0;
                sh_y[b][1] = y1;
                int gb = base + b;
                out[((size_t)gb * TT + t) * 2 + 0] = y0;
                out[((size_t)gb * TT + t) * 2 + 1] = y1;
            }
        }
        __syncthreads();
    }
}

// ---------------------------------------------------------------------------
extern "C" void kernel_launch(void* const* d_in, const int* in_sizes, int n_in,
                              void* d_out, int out_size) {
    const float* x        = (const float*)d_in[0];
    const float* ln_w     = (const float*)d_in[1];
    const float* ln_b     = (const float*)d_in[2];
    const float* enc_Wih0 = (const float*)d_in[3];
    const float* enc_Whh0 = (const float*)d_in[4];
    const float* enc_bih0 = (const float*)d_in[5];
    const float* enc_bhh0 = (const float*)d_in[6];
    const float* enc_Wih1 = (const float*)d_in[7];
    const float* enc_Whh1 = (const float*)d_in[8];
    const float* enc_bih1 = (const float*)d_in[9];
    const float* enc_bhh1 = (const float*)d_in[10];
    const float* dec_Wih0 = (const float*)d_in[11];
    const float* dec_Whh0 = (const float*)d_in[12];
    const float* dec_bih0 = (const float*)d_in[13];
    const float* dec_bhh0 = (const float*)d_in[14];
    const float* dec_Wih1 = (const float*)d_in[15];
    const float* dec_Whh1 = (const float*)d_in[16];
    const float* dec_bih1 = (const float*)d_in[17];
    const float* dec_bhh1 = (const float*)d_in[18];
    const float* fc_enc_w = (const float*)d_in[19];
    const float* fc_enc_b = (const float*)d_in[20];
    const float* fc_dec_w = (const float*)d_in[21];
    const float* fc_dec_b = (const float*)d_in[22];
    const float* fc_out_w = (const float*)d_in[23];
    const float* fc_out_b = (const float*)d_in[24];

    float* out = (float*)d_out;
    const int recon_elems = BB * TT * 2;             // 184320
    const int z_elems     = BB * LATD;               // 65536
    int write_z = (out_size >= recon_elems + z_elems) ? 1 : 0;
    float* z_out = out + recon_elems;

    enc_kernel<<<NB, 256>>>(x, ln_w, ln_b,
                            enc_Wih0, enc_Whh0, enc_bih0, enc_bhh0,
                            enc_Wih1, enc_Whh1, enc_bih1, enc_bhh1,
                            fc_enc_w, fc_enc_b, z_out, write_z);

    dec_kernel<<<NB, 256>>>(dec_Wih0, dec_Whh0, dec_bih0, dec_bhh0,
                            dec_Wih1, dec_Whh1, dec_bih1, dec_bhh1,
                            fc_dec_w, fc_dec_b, fc_out_w, fc_out_b, out);
}